// round 6
// baseline (speedup 1.0000x reference)
#include <cuda_runtime.h>

#define NCHAN 256
#define NPTS  49

// Channel-interleaved HWC scratch for image 0, levels 3..5.
// slot(pix, phase, l, k) = pix*256 + phase*128 + 4*l + k  holds original channel
// phase*128 + 32*k + l   (l in [0,32), k in [0,4), phase in {0,1})
#define OFF_L3 0
#define OFF_L4 (16384 * 256)
#define OFF_L5 (OFF_L4 + 4096 * 256)
#define SCRATCH_ELEMS (OFF_L5 + 1024 * 256)
__device__ __align__(16) float g_scratch[SCRATCH_ELEMS];

// ---- fused CHW -> interleaved-HWC transpose for levels 3,4,5 (image 0) ----
// block: 32 pixels x 128 original channels (one phase). 256 threads.
// blocks: L3 = 512*2 = 1024, L4 = 128*2 = 256, L5 = 32*2 = 64  -> 1344
__global__ __launch_bounds__(256) void tpose_all(const float* __restrict__ p3,
                                                 const float* __restrict__ p4,
                                                 const float* __restrict__ p5) {
    __shared__ float tile[128][33];
    int b = blockIdx.x;
    const float* in;
    float* op;
    int HW;
    if (b < 1024)      { in = p3; op = g_scratch + OFF_L3; HW = 16384; }
    else if (b < 1280) { b -= 1024; in = p4; op = g_scratch + OFF_L4; HW = 4096; }
    else               { b -= 1280; in = p5; op = g_scratch + OFF_L5; HW = 1024; }
    int xt    = b >> 1;        // pixel tile (32 px)
    int phase = b & 1;         // channel half

    int tx = threadIdx.x, ty = threadIdx.y;
    int x = xt * 32 + tx;
    #pragma unroll
    for (int j = ty; j < 128; j += 8)
        tile[j][tx] = __ldcs(in + (phase * 128 + j) * HW + x);
    __syncthreads();

    int pbase = xt * 32;
    #pragma unroll
    for (int px = ty; px < 32; px += 8) {
        float4 v;
        v.x = tile[tx      ][px];
        v.y = tile[tx + 32 ][px];
        v.z = tile[tx + 64 ][px];
        v.w = tile[tx + 96 ][px];
        *(float4*)(op + (pbase + px) * NCHAN + phase * 128 + 4 * tx) = v;
    }
}

// ---- pooling: vectorized HWC gathers for levels 3-5, NCHW path for level 2 ----
__global__ __launch_bounds__(256) void roi_pool(const float* __restrict__ p2,
                                                const float* __restrict__ rois,
                                                float* __restrict__ out) {
    __shared__ __align__(16) float sout[128 * NPTS];  // one phase (128 ch x 49 pts)
    __shared__ int   s_oTL[NPTS], s_oTR[NPTS], s_oBL[NPTS], s_oBR[NPTS];
    __shared__ float s_lx[NPTS], s_ly[NPTS], s_m[NPTS];

    int n   = blockIdx.x;
    int tid = threadIdx.x;

    float rx1 = __ldg(rois + 4 * n + 0);
    float ry1 = __ldg(rois + 4 * n + 1);
    float rx2 = __ldg(rois + 4 * n + 2);
    float ry2 = __ldg(rois + 4 * n + 3);

    float area = (ry2 - ry1) * (rx2 - rx1);
    float lvlf = log2f(sqrtf(fmaxf(area, 0.0f)) / 224.0f);
    int level = (int)rintf(lvlf) + 4;          // half-even, matches jnp.round
    level = min(5, max(2, level));
    int W = 1024 >> level;                     // H == W

    if (tid < NPTS) {
        float scale = (float)(W - 1);
        float ny1 = ry1 * (1.0f / 1024.0f);
        float nx1 = rx1 * (1.0f / 1024.0f);
        float dy  = __fsub_rn(ry2 * (1.0f / 1024.0f), ny1);
        float dx  = __fsub_rn(rx2 * (1.0f / 1024.0f), nx1);

        int py = tid / 7;
        int px = tid - py * 7;

        float ty = (float)py / 6.0f;
        float ys = __fmul_rn(__fadd_rn(ny1, __fmul_rn(ty, dy)), scale);
        bool  vy = (ys >= 0.0f) && (ys <= scale);
        float ysc = fminf(fmaxf(ys, 0.0f), scale);
        int   y0  = (int)floorf(ysc);
        int   y1i = min(y0 + 1, W - 1);
        float ly  = __fsub_rn(ysc, (float)y0);

        float tx = (float)px / 6.0f;
        float xs = __fmul_rn(__fadd_rn(nx1, __fmul_rn(tx, dx)), scale);
        bool  vx = (xs >= 0.0f) && (xs <= scale);
        float xsc = fminf(fmaxf(xs, 0.0f), scale);
        int   x0  = (int)floorf(xsc);
        int   x1i = min(x0 + 1, W - 1);
        float lx  = __fsub_rn(xsc, (float)x0);

        s_oTL[tid] = y0  * W + x0;
        s_oTR[tid] = y0  * W + x1i;
        s_oBL[tid] = y1i * W + x0;
        s_oBR[tid] = y1i * W + x1i;
        s_lx[tid] = lx;
        s_ly[tid] = ly;
        s_m[tid]  = (vy && vx) ? 1.0f : 0.0f;
    }
    __syncthreads();

    long obase = (long)n * (NCHAN * NPTS);

    if (level >= 3) {
        const float* fm = g_scratch +
            ((level == 3) ? OFF_L3 : (level == 4) ? OFF_L4 : OFF_L5);
        int warpid = tid >> 5;
        int lane   = tid & 31;

        #pragma unroll
        for (int phase = 0; phase < 2; phase++) {
            int pbias = phase * 128 + 4 * lane;
            #pragma unroll 2
            for (int pt = warpid; pt < NPTS; pt += 8) {
                const float4 tl4 = *(const float4*)(fm + s_oTL[pt] * NCHAN + pbias);
                const float4 tr4 = *(const float4*)(fm + s_oTR[pt] * NCHAN + pbias);
                const float4 bl4 = *(const float4*)(fm + s_oBL[pt] * NCHAN + pbias);
                const float4 br4 = *(const float4*)(fm + s_oBR[pt] * NCHAN + pbias);
                float lx = s_lx[pt], ly = s_ly[pt], m = s_m[pt];

                const float* tl = (const float*)&tl4;
                const float* tr = (const float*)&tr4;
                const float* bl = (const float*)&bl4;
                const float* br = (const float*)&br4;
                #pragma unroll
                for (int k = 0; k < 4; k++) {
                    float top = fmaf(tr[k] - tl[k], lx, tl[k]);
                    float bot = fmaf(br[k] - bl[k], lx, bl[k]);
                    // component k holds (in-phase) channel 32*k + lane
                    sout[(k * 32 + lane) * NPTS + pt] = fmaf(bot - top, ly, top) * m;
                }
            }
            __syncthreads();
            const float4* s4 = (const float4*)sout;
            float4* o4 = (float4*)(out + obase + phase * (128 * NPTS));
            #pragma unroll
            for (int i = tid; i < 128 * NPTS / 4; i += 256)
                __stcs(o4 + i, s4[i]);
            __syncthreads();
        }
    } else {
        // level 2: gather directly from NCHW p2 (image 0, plane 65536, W=256)
        int pt = tid & 63;   // 49 active
        int cg = tid >> 6;   // 0..3
        if (pt < NPTS) {
            int oTL = s_oTL[pt], oTR = s_oTR[pt], oBL = s_oBL[pt], oBR = s_oBR[pt];
            float lx = s_lx[pt], ly = s_ly[pt], m = s_m[pt];
            #pragma unroll 4
            for (int c = cg; c < NCHAN; c += 4) {
                const float* fc = p2 + c * 65536;
                float tl = __ldg(fc + oTL);
                float tr = __ldg(fc + oTR);
                float bl = __ldg(fc + oBL);
                float br = __ldg(fc + oBR);
                float top = fmaf(tr - tl, lx, tl);
                float bot = fmaf(br - bl, lx, bl);
                __stcs(&out[obase + (long)c * NPTS + pt], fmaf(bot - top, ly, top) * m);
            }
        }
    }
}

extern "C" void kernel_launch(void* const* d_in, const int* in_sizes, int n_in,
                              void* d_out, int out_size) {
    const float* p2   = (const float*)d_in[0];
    const float* p3   = (const float*)d_in[1];
    const float* p4   = (const float*)d_in[2];
    const float* p5   = (const float*)d_in[3];
    const float* rois = (const float*)d_in[4];
    float* out = (float*)d_out;

    tpose_all<<<1344, dim3(32, 8)>>>(p3, p4, p5);

    int nrois = in_sizes[4] / 4;   // B*R
    roi_pool<<<nrois, 256>>>(p2, rois, out);
}

// round 7
// speedup vs baseline: 1.0282x; 1.0282x over previous
#include <cuda_runtime.h>

#define NCHAN 256
#define NPTS  49

// Channel-interleaved HWC scratch for image 0, levels 3..5.
// slot(pix, phase, l, k) = pix*256 + phase*128 + 4*l + k  holds original channel
// phase*128 + 32*k + l
#define OFF_L3 0
#define OFF_L4 (16384 * 256)
#define OFF_L5 (OFF_L4 + 4096 * 256)
#define SCRATCH_ELEMS (OFF_L5 + 1024 * 256)
__device__ __align__(16) float g_scratch[SCRATCH_ELEMS];

// ---- fused CHW -> interleaved-HWC transpose for levels 3,4,5 (image 0) ----
// block: 32 pixels x 128 original channels (one phase), 512 threads.
__global__ __launch_bounds__(512) void tpose_all(const float* __restrict__ p3,
                                                 const float* __restrict__ p4,
                                                 const float* __restrict__ p5) {
    __shared__ float tile[128][33];
    int b = blockIdx.x;
    const float* in;
    float* op;
    int HW;
    if (b < 1024)      { in = p3; op = g_scratch + OFF_L3; HW = 16384; }
    else if (b < 1280) { b -= 1024; in = p4; op = g_scratch + OFF_L4; HW = 4096; }
    else               { b -= 1280; in = p5; op = g_scratch + OFF_L5; HW = 1024; }
    int xt    = b >> 1;        // pixel tile (32 px)
    int phase = b & 1;         // channel half

    int tx = threadIdx.x, ty = threadIdx.y;   // 32 x 16
    int x = xt * 32 + tx;
    #pragma unroll
    for (int j = ty; j < 128; j += 16)
        tile[j][tx] = __ldcs(in + (phase * 128 + j) * HW + x);
    __syncthreads();

    int pbase = xt * 32;
    #pragma unroll
    for (int px = ty; px < 32; px += 16) {
        float4 v;
        v.x = tile[tx      ][px];
        v.y = tile[tx + 32 ][px];
        v.z = tile[tx + 64 ][px];
        v.w = tile[tx + 96 ][px];
        *(float4*)(op + (pbase + px) * NCHAN + phase * 128 + 4 * tx) = v;
    }
}

// ---- pooling: vectorized HWC gathers for levels 3-5, NCHW path for level 2 ----
__global__ __launch_bounds__(512) void roi_pool(const float* __restrict__ p2,
                                                const float* __restrict__ rois,
                                                float* __restrict__ out) {
    __shared__ __align__(16) float sout[NCHAN * NPTS];  // 49KB, flat == output layout
    __shared__ int   s_oTL[NPTS], s_oTR[NPTS], s_oBL[NPTS], s_oBR[NPTS];
    __shared__ float s_lx[NPTS], s_ly[NPTS], s_m[NPTS];

    int n   = blockIdx.x;
    int tid = threadIdx.x;

    float rx1 = __ldg(rois + 4 * n + 0);
    float ry1 = __ldg(rois + 4 * n + 1);
    float rx2 = __ldg(rois + 4 * n + 2);
    float ry2 = __ldg(rois + 4 * n + 3);

    float area = (ry2 - ry1) * (rx2 - rx1);
    float lvlf = log2f(sqrtf(fmaxf(area, 0.0f)) / 224.0f);
    int level = (int)rintf(lvlf) + 4;          // half-even, matches jnp.round
    level = min(5, max(2, level));
    int W = 1024 >> level;                     // H == W

    if (tid < NPTS) {
        float scale = (float)(W - 1);
        float ny1 = ry1 * (1.0f / 1024.0f);
        float nx1 = rx1 * (1.0f / 1024.0f);
        float dy  = __fsub_rn(ry2 * (1.0f / 1024.0f), ny1);
        float dx  = __fsub_rn(rx2 * (1.0f / 1024.0f), nx1);

        int py = tid / 7;
        int px = tid - py * 7;

        float ty = (float)py / 6.0f;
        float ys = __fmul_rn(__fadd_rn(ny1, __fmul_rn(ty, dy)), scale);
        bool  vy = (ys >= 0.0f) && (ys <= scale);
        float ysc = fminf(fmaxf(ys, 0.0f), scale);
        int   y0  = (int)floorf(ysc);
        int   y1i = min(y0 + 1, W - 1);
        float ly  = __fsub_rn(ysc, (float)y0);

        float tx = (float)px / 6.0f;
        float xs = __fmul_rn(__fadd_rn(nx1, __fmul_rn(tx, dx)), scale);
        bool  vx = (xs >= 0.0f) && (xs <= scale);
        float xsc = fminf(fmaxf(xs, 0.0f), scale);
        int   x0  = (int)floorf(xsc);
        int   x1i = min(x0 + 1, W - 1);
        float lx  = __fsub_rn(xsc, (float)x0);

        s_oTL[tid] = y0  * W + x0;
        s_oTR[tid] = y0  * W + x1i;
        s_oBL[tid] = y1i * W + x0;
        s_oBR[tid] = y1i * W + x1i;
        s_lx[tid] = lx;
        s_ly[tid] = ly;
        s_m[tid]  = (vy && vx) ? 1.0f : 0.0f;
    }
    __syncthreads();

    long obase = (long)n * (NCHAN * NPTS);

    if (level >= 3) {
        const float* fm = g_scratch +
            ((level == 3) ? OFF_L3 : (level == 4) ? OFF_L4 : OFF_L5);
        int warpid = tid >> 5;       // 0..15
        int lane   = tid & 31;
        int phase  = warpid >> 3;    // warps 0-7 -> phase 0, 8-15 -> phase 1
        int wslot  = warpid & 7;
        int pbias  = phase * 128 + 4 * lane;
        float* sph = sout + phase * (128 * NPTS);

        #pragma unroll 2
        for (int pt = wslot; pt < NPTS; pt += 8) {
            const float4 tl4 = *(const float4*)(fm + s_oTL[pt] * NCHAN + pbias);
            const float4 tr4 = *(const float4*)(fm + s_oTR[pt] * NCHAN + pbias);
            const float4 bl4 = *(const float4*)(fm + s_oBL[pt] * NCHAN + pbias);
            const float4 br4 = *(const float4*)(fm + s_oBR[pt] * NCHAN + pbias);
            float lx = s_lx[pt], ly = s_ly[pt], m = s_m[pt];

            const float* tl = (const float*)&tl4;
            const float* tr = (const float*)&tr4;
            const float* bl = (const float*)&bl4;
            const float* br = (const float*)&br4;
            #pragma unroll
            for (int k = 0; k < 4; k++) {
                float top = fmaf(tr[k] - tl[k], lx, tl[k]);
                float bot = fmaf(br[k] - bl[k], lx, bl[k]);
                sph[(k * 32 + lane) * NPTS + pt] = fmaf(bot - top, ly, top) * m;
            }
        }
        __syncthreads();

        const float4* s4 = (const float4*)sout;
        float4* o4 = (float4*)(out + obase);
        #pragma unroll
        for (int i = tid; i < NCHAN * NPTS / 4; i += 512)
            __stcs(o4 + i, s4[i]);
    } else {
        // level 2: gather directly from NCHW p2 (image 0, plane 65536, W=256)
        int pt = tid & 63;   // 49 active
        int cg = tid >> 6;   // 0..7
        if (pt < NPTS) {
            int oTL = s_oTL[pt], oTR = s_oTR[pt], oBL = s_oBL[pt], oBR = s_oBR[pt];
            float lx = s_lx[pt], ly = s_ly[pt], m = s_m[pt];
            #pragma unroll 4
            for (int c = cg; c < NCHAN; c += 8) {
                const float* fc = p2 + c * 65536;
                float tl = __ldg(fc + oTL);
                float tr = __ldg(fc + oTR);
                float bl = __ldg(fc + oBL);
                float br = __ldg(fc + oBR);
                float top = fmaf(tr - tl, lx, tl);
                float bot = fmaf(br - bl, lx, bl);
                __stcs(&out[obase + (long)c * NPTS + pt], fmaf(bot - top, ly, top) * m);
            }
        }
    }
}

extern "C" void kernel_launch(void* const* d_in, const int* in_sizes, int n_in,
                              void* d_out, int out_size) {
    const float* p2   = (const float*)d_in[0];
    const float* p3   = (const float*)d_in[1];
    const float* p4   = (const float*)d_in[2];
    const float* p5   = (const float*)d_in[3];
    const float* rois = (const float*)d_in[4];
    float* out = (float*)d_out;

    tpose_all<<<1344, dim3(32, 16)>>>(p3, p4, p5);

    int nrois = in_sizes[4] / 4;   // B*R
    roi_pool<<<nrois, 512>>>(p2, rois, out);
}